// round 2
// baseline (speedup 1.0000x reference)
#include <cuda_runtime.h>
#include <cuda_bf16.h>
#include <math.h>

// Problem constants
#define BATCH   2
#define SEQ     2048
#define DMODEL  1024
#define NHEADS  16
#define DK      64
#define MROWS   (BATCH * SEQ)      // 4096

// ---------------------------------------------------------------------------
// Scratch (device globals — no allocation allowed)
// ---------------------------------------------------------------------------
__device__ float g_q[MROWS * DMODEL];
__device__ float g_k[MROWS * DMODEL];
__device__ float g_v[MROWS * DMODEL];
__device__ float g_ctx[MROWS * DMODEL];

// ---------------------------------------------------------------------------
// SGEMM: C[M,N] = A[M,K] @ W[N,K]^T + bias[N]
// Tiles: BM=128, BN=128, BK=16; 256 threads; 8x8 per thread.
// A and W tiles are transposed into smem (k-major) so the inner loop does
// conflict-free LDS.128 fragment loads.
// ---------------------------------------------------------------------------
#define BM 128
#define BN 128
#define BK 16

__global__ __launch_bounds__(256, 2)
void sgemm_bias(const float* __restrict__ A,
                const float* __restrict__ W,
                const float* __restrict__ bias,
                float* __restrict__ C,
                int M, int N, int K) {
    __shared__ float As[BK][BM];
    __shared__ float Bs[BK][BN];

    const int bx = blockIdx.x;            // N tile
    const int by = blockIdx.y;            // M tile
    const int tid = threadIdx.x;
    const int tx = tid & 15;              // 0..15
    const int ty = tid >> 4;              // 0..15

    // Load mapping: 128 rows x 16 k per tile; each thread loads 8 floats (2 x float4)
    const int lrow = tid >> 1;            // 0..127
    const int lk   = (tid & 1) * 8;       // 0 or 8

    const float* Ag = A + (size_t)(by * BM + lrow) * K;
    const float* Wg = W + (size_t)(bx * BN + lrow) * K;

    float acc[8][8];
    #pragma unroll
    for (int i = 0; i < 8; i++)
        #pragma unroll
        for (int j = 0; j < 8; j++) acc[i][j] = 0.0f;

    for (int k0 = 0; k0 < K; k0 += BK) {
        float4 a0 = *(const float4*)(Ag + k0 + lk);
        float4 a1 = *(const float4*)(Ag + k0 + lk + 4);
        float4 b0 = *(const float4*)(Wg + k0 + lk);
        float4 b1 = *(const float4*)(Wg + k0 + lk + 4);

        __syncthreads();   // previous tile's compute is done
        As[lk + 0][lrow] = a0.x; As[lk + 1][lrow] = a0.y;
        As[lk + 2][lrow] = a0.z; As[lk + 3][lrow] = a0.w;
        As[lk + 4][lrow] = a1.x; As[lk + 5][lrow] = a1.y;
        As[lk + 6][lrow] = a1.z; As[lk + 7][lrow] = a1.w;
        Bs[lk + 0][lrow] = b0.x; Bs[lk + 1][lrow] = b0.y;
        Bs[lk + 2][lrow] = b0.z; Bs[lk + 3][lrow] = b0.w;
        Bs[lk + 4][lrow] = b1.x; Bs[lk + 5][lrow] = b1.y;
        Bs[lk + 6][lrow] = b1.z; Bs[lk + 7][lrow] = b1.w;
        __syncthreads();

        #pragma unroll
        for (int k = 0; k < BK; k++) {
            float4 fa0 = *(const float4*)&As[k][ty * 4];
            float4 fa1 = *(const float4*)&As[k][ty * 4 + 64];
            float4 fb0 = *(const float4*)&Bs[k][tx * 4];
            float4 fb1 = *(const float4*)&Bs[k][tx * 4 + 64];
            float av[8] = {fa0.x, fa0.y, fa0.z, fa0.w, fa1.x, fa1.y, fa1.z, fa1.w};
            float bv[8] = {fb0.x, fb0.y, fb0.z, fb0.w, fb1.x, fb1.y, fb1.z, fb1.w};
            #pragma unroll
            for (int i = 0; i < 8; i++)
                #pragma unroll
                for (int j = 0; j < 8; j++)
                    acc[i][j] = fmaf(av[i], bv[j], acc[i][j]);
        }
    }

    // Epilogue with bias
    const int cbase = bx * BN + tx * 4;
    float4 bi0 = *(const float4*)(bias + cbase);
    float4 bi1 = *(const float4*)(bias + cbase + 64);
    #pragma unroll
    for (int ii = 0; ii < 8; ii++) {
        int r = by * BM + ty * 4 + (ii & 3) + ((ii >> 2) * 64);
        float4 v0 = make_float4(acc[ii][0] + bi0.x, acc[ii][1] + bi0.y,
                                acc[ii][2] + bi0.z, acc[ii][3] + bi0.w);
        float4 v1 = make_float4(acc[ii][4] + bi1.x, acc[ii][5] + bi1.y,
                                acc[ii][6] + bi1.z, acc[ii][7] + bi1.w);
        *(float4*)(C + (size_t)r * N + cbase)      = v0;
        *(float4*)(C + (size_t)r * N + cbase + 64) = v1;
    }
}

// ---------------------------------------------------------------------------
// Flash attention (fp32, online softmax).
// Grid: (S/64, B*NHEADS). Block: 256 threads (16x16), each thread owns a
// 4x4 micro-tile of the 64x64 score tile and of the 64x64 output tile.
// Smem: Q^T [d][i], K^T [d][j], P^T [j][i] all padded to 68 floats/row
// (pad multiple of 4 keeps LDS.128 16B-aligned; stride==4 banks mod 32 keeps
// the hot-loop loads conflict-free). V [j][d] unpadded (row-major access).
// ---------------------------------------------------------------------------
#define QT 64
#define KT 64
#define PADT 68
#define ATT_SMEM ((3 * 64 * PADT + 64 * 64) * 4)

__global__ __launch_bounds__(256)
void flash_attn(const float* __restrict__ Q,
                const float* __restrict__ Km,
                const float* __restrict__ Vm,
                float* __restrict__ ctx) {
    extern __shared__ float sm[];
    float* Qst = sm;                    // [64][68] (d-major)
    float* Kst = Qst + 64 * PADT;       // [64][68] (d-major)
    float* Ps  = Kst + 64 * PADT;       // [64][68] (j-major, [j][i])
    float* Vs  = Ps  + 64 * PADT;       // [64][64] (j-major, [j][d])

    const int tid = threadIdx.x;
    const int tx  = tid & 15;
    const int ty  = tid >> 4;
    const int qt  = blockIdx.x;         // q tile (0..31)
    const int bh  = blockIdx.y;         // 0..31
    const int b   = bh >> 4;
    const int h   = bh & 15;

    const int lrow = tid >> 2;          // 0..63
    const int lc   = (tid & 3) * 4;     // 0,4,8,12

    const float SCL = 0.125f;           // 1/sqrt(64)
    const float L2E = 1.44269504088896f;

    // ---- Load Q tile, transposed into Qst[d][i] ----
    {
        const float* Qg = Q + (size_t)(b * SEQ + qt * QT + lrow) * DMODEL + h * DK;
        #pragma unroll
        for (int v = 0; v < 4; v++) {
            int d0 = lc + 16 * v;
            float4 t = *(const float4*)(Qg + d0);
            Qst[(d0 + 0) * PADT + lrow] = t.x;
            Qst[(d0 + 1) * PADT + lrow] = t.y;
            Qst[(d0 + 2) * PADT + lrow] = t.z;
            Qst[(d0 + 3) * PADT + lrow] = t.w;
        }
    }

    float acc[4][4];
    float m[4], l[4];
    #pragma unroll
    for (int i = 0; i < 4; i++) {
        m[i] = -1e30f; l[i] = 0.0f;
        #pragma unroll
        for (int j = 0; j < 4; j++) acc[i][j] = 0.0f;
    }

    for (int kt = 0; kt < SEQ / KT; kt++) {
        __syncthreads();   // previous iteration's PV reads done

        // ---- Load K tile (transposed) and V tile ----
        {
            const float* Kg = Km + (size_t)(b * SEQ + kt * KT + lrow) * DMODEL + h * DK;
            const float* Vg = Vm + (size_t)(b * SEQ + kt * KT + lrow) * DMODEL + h * DK;
            #pragma unroll
            for (int v = 0; v < 4; v++) {
                int d0 = lc + 16 * v;
                float4 tk = *(const float4*)(Kg + d0);
                Kst[(d0 + 0) * PADT + lrow] = tk.x;
                Kst[(d0 + 1) * PADT + lrow] = tk.y;
                Kst[(d0 + 2) * PADT + lrow] = tk.z;
                Kst[(d0 + 3) * PADT + lrow] = tk.w;
                *(float4*)(Vs + lrow * 64 + d0) = *(const float4*)(Vg + d0);
            }
        }
        __syncthreads();

        // ---- S = Q K^T ----
        float s[4][4];
        #pragma unroll
        for (int i = 0; i < 4; i++)
            #pragma unroll
            for (int j = 0; j < 4; j++) s[i][j] = 0.0f;

        #pragma unroll 8
        for (int d = 0; d < DK; d++) {
            float4 qa = *(const float4*)(Qst + d * PADT + ty * 4);
            float4 kb = *(const float4*)(Kst + d * PADT + tx * 4);
            float av[4] = {qa.x, qa.y, qa.z, qa.w};
            float bv[4] = {kb.x, kb.y, kb.z, kb.w};
            #pragma unroll
            for (int i = 0; i < 4; i++)
                #pragma unroll
                for (int j = 0; j < 4; j++)
                    s[i][j] = fmaf(av[i], bv[j], s[i][j]);
        }

        // ---- Online softmax update ----
        #pragma unroll
        for (int i = 0; i < 4; i++) {
            #pragma unroll
            for (int j = 0; j < 4; j++) s[i][j] *= SCL;

            float tmax = fmaxf(fmaxf(s[i][0], s[i][1]), fmaxf(s[i][2], s[i][3]));
            #pragma unroll
            for (int ofs = 1; ofs < 16; ofs <<= 1)
                tmax = fmaxf(tmax, __shfl_xor_sync(0xffffffffu, tmax, ofs));

            float mnew = fmaxf(m[i], tmax);
            float corr = exp2f((m[i] - mnew) * L2E);
            m[i] = mnew;

            float rsum = 0.0f;
            #pragma unroll
            for (int j = 0; j < 4; j++) {
                float p = exp2f((s[i][j] - mnew) * L2E);
                s[i][j] = p;
                rsum += p;
            }
            #pragma unroll
            for (int ofs = 1; ofs < 16; ofs <<= 1)
                rsum += __shfl_xor_sync(0xffffffffu, rsum, ofs);

            l[i] = l[i] * corr + rsum;
            #pragma unroll
            for (int c = 0; c < 4; c++) acc[i][c] *= corr;
        }

        // ---- Stage P (transposed: Ps[j][i]) ----
        #pragma unroll
        for (int j = 0; j < 4; j++)
            #pragma unroll
            for (int i = 0; i < 4; i++)
                Ps[(tx * 4 + j) * PADT + ty * 4 + i] = s[i][j];
        __syncthreads();

        // ---- acc += P @ V ----
        #pragma unroll 8
        for (int j = 0; j < KT; j++) {
            float4 pa = *(const float4*)(Ps + j * PADT + ty * 4);
            float4 vb = *(const float4*)(Vs + j * 64 + tx * 4);
            float av[4] = {pa.x, pa.y, pa.z, pa.w};
            float bv[4] = {vb.x, vb.y, vb.z, vb.w};
            #pragma unroll
            for (int i = 0; i < 4; i++)
                #pragma unroll
                for (int c = 0; c < 4; c++)
                    acc[i][c] = fmaf(av[i], bv[c], acc[i][c]);
        }
    }

    // ---- Write ctx ----
    #pragma unroll
    for (int i = 0; i < 4; i++) {
        float inv = 1.0f / l[i];
        int gr = b * SEQ + qt * QT + ty * 4 + i;
        float4 o = make_float4(acc[i][0] * inv, acc[i][1] * inv,
                               acc[i][2] * inv, acc[i][3] * inv);
        *(float4*)(ctx + (size_t)gr * DMODEL + h * DK + tx * 4) = o;
    }
}

// ---------------------------------------------------------------------------
// Launch
// ---------------------------------------------------------------------------
extern "C" void kernel_launch(void* const* d_in, const int* in_sizes, int n_in,
                              void* d_out, int out_size) {
    const float* q   = (const float*)d_in[0];
    const float* k   = (const float*)d_in[1];
    const float* v   = (const float*)d_in[2];
    const float* w_q = (const float*)d_in[3];
    const float* w_k = (const float*)d_in[4];
    const float* w_v = (const float*)d_in[5];
    const float* w_o = (const float*)d_in[6];
    const float* b_q = (const float*)d_in[7];
    const float* b_k = (const float*)d_in[8];
    const float* b_v = (const float*)d_in[9];
    const float* b_o = (const float*)d_in[10];
    float* out = (float*)d_out;

    float *gq, *gk, *gv, *gctx;
    cudaGetSymbolAddress((void**)&gq,   g_q);
    cudaGetSymbolAddress((void**)&gk,   g_k);
    cudaGetSymbolAddress((void**)&gv,   g_v);
    cudaGetSymbolAddress((void**)&gctx, g_ctx);

    cudaFuncSetAttribute(flash_attn, cudaFuncAttributeMaxDynamicSharedMemorySize, ATT_SMEM);

    dim3 gg(DMODEL / BN, MROWS / BM);   // (8, 32)

    sgemm_bias<<<gg, 256>>>(q, w_q, b_q, gq, MROWS, DMODEL, DMODEL);
    sgemm_bias<<<gg, 256>>>(k, w_k, b_k, gk, MROWS, DMODEL, DMODEL);
    sgemm_bias<<<gg, 256>>>(v, w_v, b_v, gv, MROWS, DMODEL, DMODEL);

    dim3 ag(SEQ / QT, BATCH * NHEADS);  // (32, 32)
    flash_attn<<<ag, 256, ATT_SMEM>>>(gq, gk, gv, gctx);

    sgemm_bias<<<gg, 256>>>(gctx, w_o, b_o, out, MROWS, DMODEL, DMODEL);
}

// round 4
// speedup vs baseline: 1.2808x; 1.2808x over previous
#include <cuda_runtime.h>
#include <cuda_bf16.h>
#include <math.h>
#include <cstdint>

// Problem constants
#define BATCH   2
#define SEQ     2048
#define DMODEL  1024
#define NHEADS  16
#define DK      64
#define MROWS   (BATCH * SEQ)      // 4096

// ---------------------------------------------------------------------------
// Scratch (device globals — no allocation allowed)
// ---------------------------------------------------------------------------
__device__ float g_q[MROWS * DMODEL];
__device__ float g_k[MROWS * DMODEL];
__device__ float g_v[MROWS * DMODEL];
__device__ float g_ctx[MROWS * DMODEL];

__device__ __forceinline__ uint32_t f2tf32(float f) {
    uint32_t u;
    asm("cvt.rna.tf32.f32 %0, %1;" : "=r"(u) : "f"(f));
    return u;
}

// mma.sync m16n8k8 tf32: D = A(16x8) * B(8x8) + D, fp32 accum.
__device__ __forceinline__ void mma_tf32(float* d, const uint32_t* a, const uint32_t* b) {
    asm volatile(
        "mma.sync.aligned.m16n8k8.row.col.f32.tf32.tf32.f32 "
        "{%0,%1,%2,%3}, {%4,%5,%6,%7}, {%8,%9}, {%0,%1,%2,%3};"
        : "+f"(d[0]), "+f"(d[1]), "+f"(d[2]), "+f"(d[3])
        : "r"(a[0]), "r"(a[1]), "r"(a[2]), "r"(a[3]),
          "r"(b[0]), "r"(b[1]));
}

// ---------------------------------------------------------------------------
// Tensor-core GEMM via mma.sync tf32: C[M,N] = A[M,K] @ W[N,K]^T + bias[N]
// CTA tile 128x128, BK=16. 8 warps, each computes a 64x32 warp tile via
// 4(m) x 4(n) m16n8k8 fragments per k=8 step.
// Smem is k-major [16][136]: row stride 136 floats -> bank stride 8, making
// the fragment loads (addr = (k+t)*136 + base + g, t=lane&3, g=lane>>2)
// conflict-free: banks = 8t + g + const, all 32 distinct.
// Inputs pre-rounded to tf32 (cvt.rna) at smem-store time.
// ---------------------------------------------------------------------------
#define GBK  16
#define ASTR 136

__global__ __launch_bounds__(256, 2)
void gemm_mma(const float* __restrict__ A,
              const float* __restrict__ W,
              const float* __restrict__ bias,
              float* __restrict__ C) {
    __shared__ uint32_t As[GBK][ASTR];
    __shared__ uint32_t Bs[GBK][ASTR];

    const int tid  = threadIdx.x;
    const int lane = tid & 31;
    const int wid  = tid >> 5;
    const int g    = lane >> 2;     // 0..7
    const int t    = lane & 3;      // 0..3
    const int wr   = wid >> 2;      // 0..1  (64-row half)
    const int wc   = wid & 3;       // 0..3  (32-col quarter)
    const int bx   = blockIdx.x;    // N tile
    const int by   = blockIdx.y;    // M tile

    // loader mapping: 128 rows x 16 k; each thread 8 floats (2 float4) per operand
    const int lrow = tid >> 1;          // 0..127
    const int lk   = (tid & 1) * 8;     // 0 or 8

    const float* Ag = A + (size_t)(by * 128 + lrow) * DMODEL;
    const float* Wg = W + (size_t)(bx * 128 + lrow) * DMODEL;

    float acc[4][4][4];
    #pragma unroll
    for (int mi = 0; mi < 4; mi++)
        #pragma unroll
        for (int ni = 0; ni < 4; ni++)
            #pragma unroll
            for (int r = 0; r < 4; r++) acc[mi][ni][r] = 0.0f;

    for (int k0 = 0; k0 < DMODEL; k0 += GBK) {
        float4 a0 = *(const float4*)(Ag + k0 + lk);
        float4 a1 = *(const float4*)(Ag + k0 + lk + 4);
        float4 b0 = *(const float4*)(Wg + k0 + lk);
        float4 b1 = *(const float4*)(Wg + k0 + lk + 4);

        __syncthreads();   // previous tile's compute done
        As[lk + 0][lrow] = f2tf32(a0.x); As[lk + 1][lrow] = f2tf32(a0.y);
        As[lk + 2][lrow] = f2tf32(a0.z); As[lk + 3][lrow] = f2tf32(a0.w);
        As[lk + 4][lrow] = f2tf32(a1.x); As[lk + 5][lrow] = f2tf32(a1.y);
        As[lk + 6][lrow] = f2tf32(a1.z); As[lk + 7][lrow] = f2tf32(a1.w);
        Bs[lk + 0][lrow] = f2tf32(b0.x); Bs[lk + 1][lrow] = f2tf32(b0.y);
        Bs[lk + 2][lrow] = f2tf32(b0.z); Bs[lk + 3][lrow] = f2tf32(b0.w);
        Bs[lk + 4][lrow] = f2tf32(b1.x); Bs[lk + 5][lrow] = f2tf32(b1.y);
        Bs[lk + 6][lrow] = f2tf32(b1.z); Bs[lk + 7][lrow] = f2tf32(b1.w);
        __syncthreads();

        #pragma unroll
        for (int ks = 0; ks < GBK; ks += 8) {
            uint32_t afr[4][4];
            #pragma unroll
            for (int mi = 0; mi < 4; mi++) {
                const int rb = wr * 64 + mi * 16 + g;
                afr[mi][0] = As[ks + t    ][rb];
                afr[mi][1] = As[ks + t    ][rb + 8];
                afr[mi][2] = As[ks + t + 4][rb];
                afr[mi][3] = As[ks + t + 4][rb + 8];
            }
            uint32_t bfr[4][2];
            #pragma unroll
            for (int ni = 0; ni < 4; ni++) {
                const int cb = wc * 32 + ni * 8 + g;
                bfr[ni][0] = Bs[ks + t    ][cb];
                bfr[ni][1] = Bs[ks + t + 4][cb];
            }
            #pragma unroll
            for (int mi = 0; mi < 4; mi++)
                #pragma unroll
                for (int ni = 0; ni < 4; ni++)
                    mma_tf32(acc[mi][ni], afr[mi], bfr[ni]);
        }
    }

    // Epilogue: c0=(g,2t) c1=(g,2t+1) c2=(g+8,2t) c3=(g+8,2t+1) per fragment
    #pragma unroll
    for (int mi = 0; mi < 4; mi++) {
        const int r0 = by * 128 + wr * 64 + mi * 16 + g;
        #pragma unroll
        for (int ni = 0; ni < 4; ni++) {
            const int cc = bx * 128 + wc * 32 + ni * 8 + 2 * t;
            float2 bv = *(const float2*)(bias + cc);
            float2 o0 = make_float2(acc[mi][ni][0] + bv.x, acc[mi][ni][1] + bv.y);
            float2 o1 = make_float2(acc[mi][ni][2] + bv.x, acc[mi][ni][3] + bv.y);
            *(float2*)(C + (size_t)r0 * DMODEL + cc)       = o0;
            *(float2*)(C + (size_t)(r0 + 8) * DMODEL + cc) = o1;
        }
    }
}

// ---------------------------------------------------------------------------
// Flash attention (fp32, online softmax) — unchanged (passing, R2).
// ---------------------------------------------------------------------------
#define QT 64
#define KT 64
#define PADT 68
#define ATT_SMEM ((3 * 64 * PADT + 64 * 64) * 4)

__global__ __launch_bounds__(256)
void flash_attn(const float* __restrict__ Q,
                const float* __restrict__ Km,
                const float* __restrict__ Vm,
                float* __restrict__ ctx) {
    extern __shared__ float sm[];
    float* Qst = sm;                    // [64][68] (d-major)
    float* Kst = Qst + 64 * PADT;       // [64][68] (d-major)
    float* Ps  = Kst + 64 * PADT;       // [64][68] (j-major, [j][i])
    float* Vs  = Ps  + 64 * PADT;       // [64][64] (j-major, [j][d])

    const int tid = threadIdx.x;
    const int tx  = tid & 15;
    const int ty  = tid >> 4;
    const int qt  = blockIdx.x;
    const int bh  = blockIdx.y;
    const int b   = bh >> 4;
    const int h   = bh & 15;

    const int lrow = tid >> 2;
    const int lc   = (tid & 3) * 4;

    const float SCL = 0.125f;
    const float L2E = 1.44269504088896f;

    {
        const float* Qg = Q + (size_t)(b * SEQ + qt * QT + lrow) * DMODEL + h * DK;
        #pragma unroll
        for (int v = 0; v < 4; v++) {
            int d0 = lc + 16 * v;
            float4 tq = *(const float4*)(Qg + d0);
            Qst[(d0 + 0) * PADT + lrow] = tq.x;
            Qst[(d0 + 1) * PADT + lrow] = tq.y;
            Qst[(d0 + 2) * PADT + lrow] = tq.z;
            Qst[(d0 + 3) * PADT + lrow] = tq.w;
        }
    }

    float acc[4][4];
    float m[4], l[4];
    #pragma unroll
    for (int i = 0; i < 4; i++) {
        m[i] = -1e30f; l[i] = 0.0f;
        #pragma unroll
        for (int j = 0; j < 4; j++) acc[i][j] = 0.0f;
    }

    for (int kt = 0; kt < SEQ / KT; kt++) {
        __syncthreads();

        {
            const float* Kg = Km + (size_t)(b * SEQ + kt * KT + lrow) * DMODEL + h * DK;
            const float* Vg = Vm + (size_t)(b * SEQ + kt * KT + lrow) * DMODEL + h * DK;
            #pragma unroll
            for (int v = 0; v < 4; v++) {
                int d0 = lc + 16 * v;
                float4 tk = *(const float4*)(Kg + d0);
                Kst[(d0 + 0) * PADT + lrow] = tk.x;
                Kst[(d0 + 1) * PADT + lrow] = tk.y;
                Kst[(d0 + 2) * PADT + lrow] = tk.z;
                Kst[(d0 + 3) * PADT + lrow] = tk.w;
                *(float4*)(Vs + lrow * 64 + d0) = *(const float4*)(Vg + d0);
            }
        }
        __syncthreads();

        float s[4][4];
        #pragma unroll
        for (int i = 0; i < 4; i++)
            #pragma unroll
            for (int j = 0; j < 4; j++) s[i][j] = 0.0f;

        #pragma unroll 8
        for (int d = 0; d < DK; d++) {
            float4 qa = *(const float4*)(Qst + d * PADT + ty * 4);
            float4 kb = *(const float4*)(Kst + d * PADT + tx * 4);
            float av[4] = {qa.x, qa.y, qa.z, qa.w};
            float bv[4] = {kb.x, kb.y, kb.z, kb.w};
            #pragma unroll
            for (int i = 0; i < 4; i++)
                #pragma unroll
                for (int j = 0; j < 4; j++)
                    s[i][j] = fmaf(av[i], bv[j], s[i][j]);
        }

        #pragma unroll
        for (int i = 0; i < 4; i++) {
            #pragma unroll
            for (int j = 0; j < 4; j++) s[i][j] *= SCL;

            float tmax = fmaxf(fmaxf(s[i][0], s[i][1]), fmaxf(s[i][2], s[i][3]));
            #pragma unroll
            for (int ofs = 1; ofs < 16; ofs <<= 1)
                tmax = fmaxf(tmax, __shfl_xor_sync(0xffffffffu, tmax, ofs));

            float mnew = fmaxf(m[i], tmax);
            float corr = exp2f((m[i] - mnew) * L2E);
            m[i] = mnew;

            float rsum = 0.0f;
            #pragma unroll
            for (int j = 0; j < 4; j++) {
                float p = exp2f((s[i][j] - mnew) * L2E);
                s[i][j] = p;
                rsum += p;
            }
            #pragma unroll
            for (int ofs = 1; ofs < 16; ofs <<= 1)
                rsum += __shfl_xor_sync(0xffffffffu, rsum, ofs);

            l[i] = l[i] * corr + rsum;
            #pragma unroll
            for (int c = 0; c < 4; c++) acc[i][c] *= corr;
        }

        #pragma unroll
        for (int j = 0; j < 4; j++)
            #pragma unroll
            for (int i = 0; i < 4; i++)
                Ps[(tx * 4 + j) * PADT + ty * 4 + i] = s[i][j];
        __syncthreads();

        #pragma unroll 8
        for (int j = 0; j < KT; j++) {
            float4 pa = *(const float4*)(Ps + j * PADT + ty * 4);
            float4 vb = *(const float4*)(Vs + j * 64 + tx * 4);
            float av[4] = {pa.x, pa.y, pa.z, pa.w};
            float bv[4] = {vb.x, vb.y, vb.z, vb.w};
            #pragma unroll
            for (int i = 0; i < 4; i++)
                #pragma unroll
                for (int c = 0; c < 4; c++)
                    acc[i][c] = fmaf(av[i], bv[c], acc[i][c]);
        }
    }

    #pragma unroll
    for (int i = 0; i < 4; i++) {
        float inv = 1.0f / l[i];
        int gr = b * SEQ + qt * QT + ty * 4 + i;
        float4 o = make_float4(acc[i][0] * inv, acc[i][1] * inv,
                               acc[i][2] * inv, acc[i][3] * inv);
        *(float4*)(ctx + (size_t)gr * DMODEL + h * DK + tx * 4) = o;
    }
}

// ---------------------------------------------------------------------------
// Launch
// ---------------------------------------------------------------------------
extern "C" void kernel_launch(void* const* d_in, const int* in_sizes, int n_in,
                              void* d_out, int out_size) {
    const float* q   = (const float*)d_in[0];
    const float* k   = (const float*)d_in[1];
    const float* v   = (const float*)d_in[2];
    const float* w_q = (const float*)d_in[3];
    const float* w_k = (const float*)d_in[4];
    const float* w_v = (const float*)d_in[5];
    const float* w_o = (const float*)d_in[6];
    const float* b_q = (const float*)d_in[7];
    const float* b_k = (const float*)d_in[8];
    const float* b_v = (const float*)d_in[9];
    const float* b_o = (const float*)d_in[10];
    float* out = (float*)d_out;

    float *gq, *gk, *gv, *gctx;
    cudaGetSymbolAddress((void**)&gq,   g_q);
    cudaGetSymbolAddress((void**)&gk,   g_k);
    cudaGetSymbolAddress((void**)&gv,   g_v);
    cudaGetSymbolAddress((void**)&gctx, g_ctx);

    cudaFuncSetAttribute(flash_attn, cudaFuncAttributeMaxDynamicSharedMemorySize, ATT_SMEM);

    dim3 gg(DMODEL / 128, MROWS / 128);   // (8, 32)

    gemm_mma<<<gg, 256>>>(q, w_q, b_q, gq);
    gemm_mma<<<gg, 256>>>(k, w_k, b_k, gk);
    gemm_mma<<<gg, 256>>>(v, w_v, b_v, gv);

    dim3 ag(SEQ / QT, BATCH * NHEADS);    // (32, 32)
    flash_attn<<<ag, 256, ATT_SMEM>>>(gq, gk, gv, gctx);

    gemm_mma<<<gg, 256>>>(gctx, w_o, b_o, out);
}

// round 5
// speedup vs baseline: 2.1998x; 1.7175x over previous
#include <cuda_runtime.h>
#include <cuda_bf16.h>
#include <math.h>
#include <cstdint>

// Problem constants
#define BATCH   2
#define SEQ     2048
#define DMODEL  1024
#define NHEADS  16
#define DK      64
#define MROWS   (BATCH * SEQ)      // 4096

// ---------------------------------------------------------------------------
// Scratch (device globals — no allocation allowed)
// ---------------------------------------------------------------------------
__device__ float g_q[MROWS * DMODEL];
__device__ float g_k[MROWS * DMODEL];
__device__ float g_v[MROWS * DMODEL];
__device__ float g_ctx[MROWS * DMODEL];

__device__ __forceinline__ uint32_t f2tf32(float f) {
    uint32_t u;
    asm("cvt.rna.tf32.f32 %0, %1;" : "=r"(u) : "f"(f));
    return u;
}

// mma.sync m16n8k8 tf32: D = A(16x8) * B(8x8) + D, fp32 accum.
// Layouts validated in Round 4:
//   A: a0=(g,t) a1=(g+8,t) a2=(g,t+4) a3=(g+8,t+4)     [g=lane>>2, t=lane&3]
//   B: b0=(k=t,n=g) b1=(k=t+4,n=g)
//   C: c0=(g,2t) c1=(g,2t+1) c2=(g+8,2t) c3=(g+8,2t+1)
__device__ __forceinline__ void mma_tf32(float* d, const uint32_t* a, const uint32_t* b) {
    asm volatile(
        "mma.sync.aligned.m16n8k8.row.col.f32.tf32.tf32.f32 "
        "{%0,%1,%2,%3}, {%4,%5,%6,%7}, {%8,%9}, {%0,%1,%2,%3};"
        : "+f"(d[0]), "+f"(d[1]), "+f"(d[2]), "+f"(d[3])
        : "r"(a[0]), "r"(a[1]), "r"(a[2]), "r"(a[3]),
          "r"(b[0]), "r"(b[1]));
}

// Fast exp2 for x <= 0: all fixed-latency pipe ops, no MUFU, no F2I.
// Magic-constant range reduction + degree-5 poly; rel err ~2e-6.
__device__ __forceinline__ float fexp2(float x) {
    x = fmaxf(x, -126.0f);
    float t = __fadd_rn(x, 12582912.0f);       // 1.5 * 2^23
    float u = __fsub_rn(t, 12582912.0f);       // round(x)
    float f = __fsub_rn(x, u);                 // [-0.5, 0.5]
    float p = 1.3333558e-3f;
    p = fmaf(p, f, 9.6181291e-3f);
    p = fmaf(p, f, 5.5504109e-2f);
    p = fmaf(p, f, 2.4022651e-1f);
    p = fmaf(p, f, 6.9314718e-1f);
    p = fmaf(p, f, 1.0f);
    float s = __int_as_float((__float_as_int(t) << 23) + 0x3F800000);
    return p * s;
}

// ---------------------------------------------------------------------------
// Tensor-core GEMM via mma.sync tf32 (unchanged, validated R4):
// C[M,N] = A[M,K] @ W[N,K]^T + bias[N]
// ---------------------------------------------------------------------------
#define GBK  16
#define ASTR 136

__global__ __launch_bounds__(256, 2)
void gemm_mma(const float* __restrict__ A,
              const float* __restrict__ W,
              const float* __restrict__ bias,
              float* __restrict__ C) {
    __shared__ uint32_t As[GBK][ASTR];
    __shared__ uint32_t Bs[GBK][ASTR];

    const int tid  = threadIdx.x;
    const int lane = tid & 31;
    const int wid  = tid >> 5;
    const int g    = lane >> 2;
    const int t    = lane & 3;
    const int wr   = wid >> 2;
    const int wc   = wid & 3;
    const int bx   = blockIdx.x;
    const int by   = blockIdx.y;

    const int lrow = tid >> 1;
    const int lk   = (tid & 1) * 8;

    const float* Ag = A + (size_t)(by * 128 + lrow) * DMODEL;
    const float* Wg = W + (size_t)(bx * 128 + lrow) * DMODEL;

    float acc[4][4][4];
    #pragma unroll
    for (int mi = 0; mi < 4; mi++)
        #pragma unroll
        for (int ni = 0; ni < 4; ni++)
            #pragma unroll
            for (int r = 0; r < 4; r++) acc[mi][ni][r] = 0.0f;

    for (int k0 = 0; k0 < DMODEL; k0 += GBK) {
        float4 a0 = *(const float4*)(Ag + k0 + lk);
        float4 a1 = *(const float4*)(Ag + k0 + lk + 4);
        float4 b0 = *(const float4*)(Wg + k0 + lk);
        float4 b1 = *(const float4*)(Wg + k0 + lk + 4);

        __syncthreads();
        As[lk + 0][lrow] = f2tf32(a0.x); As[lk + 1][lrow] = f2tf32(a0.y);
        As[lk + 2][lrow] = f2tf32(a0.z); As[lk + 3][lrow] = f2tf32(a0.w);
        As[lk + 4][lrow] = f2tf32(a1.x); As[lk + 5][lrow] = f2tf32(a1.y);
        As[lk + 6][lrow] = f2tf32(a1.z); As[lk + 7][lrow] = f2tf32(a1.w);
        Bs[lk + 0][lrow] = f2tf32(b0.x); Bs[lk + 1][lrow] = f2tf32(b0.y);
        Bs[lk + 2][lrow] = f2tf32(b0.z); Bs[lk + 3][lrow] = f2tf32(b0.w);
        Bs[lk + 4][lrow] = f2tf32(b1.x); Bs[lk + 5][lrow] = f2tf32(b1.y);
        Bs[lk + 6][lrow] = f2tf32(b1.z); Bs[lk + 7][lrow] = f2tf32(b1.w);
        __syncthreads();

        #pragma unroll
        for (int ks = 0; ks < GBK; ks += 8) {
            uint32_t afr[4][4];
            #pragma unroll
            for (int mi = 0; mi < 4; mi++) {
                const int rb = wr * 64 + mi * 16 + g;
                afr[mi][0] = As[ks + t    ][rb];
                afr[mi][1] = As[ks + t    ][rb + 8];
                afr[mi][2] = As[ks + t + 4][rb];
                afr[mi][3] = As[ks + t + 4][rb + 8];
            }
            uint32_t bfr[4][2];
            #pragma unroll
            for (int ni = 0; ni < 4; ni++) {
                const int cb = wc * 32 + ni * 8 + g;
                bfr[ni][0] = Bs[ks + t    ][cb];
                bfr[ni][1] = Bs[ks + t + 4][cb];
            }
            #pragma unroll
            for (int mi = 0; mi < 4; mi++)
                #pragma unroll
                for (int ni = 0; ni < 4; ni++)
                    mma_tf32(acc[mi][ni], afr[mi], bfr[ni]);
        }
    }

    #pragma unroll
    for (int mi = 0; mi < 4; mi++) {
        const int r0 = by * 128 + wr * 64 + mi * 16 + g;
        #pragma unroll
        for (int ni = 0; ni < 4; ni++) {
            const int cc = bx * 128 + wc * 32 + ni * 8 + 2 * t;
            float2 bv = *(const float2*)(bias + cc);
            float2 o0 = make_float2(acc[mi][ni][0] + bv.x, acc[mi][ni][1] + bv.y);
            float2 o1 = make_float2(acc[mi][ni][2] + bv.x, acc[mi][ni][3] + bv.y);
            *(float2*)(C + (size_t)r0 * DMODEL + cc)       = o0;
            *(float2*)(C + (size_t)(r0 + 8) * DMODEL + cc) = o1;
        }
    }
}

// ---------------------------------------------------------------------------
// Flash attention with mma.sync tf32 for QK^T and PV; FFMA-poly softmax.
// CTA: 256 threads (8 warps), 128 q-rows; warp w owns rows 16w..16w+15.
// KT=64 keys per mainloop tile.
// Smem strides chosen for conflict-free fragment LDS:
//   Qs/Ks/Ps stride 68 (bank = 4g+t+8ks, distinct); Vs stride 72 (bank = 8t+g).
// Q is pre-scaled by 0.125*log2(e) before tf32 rounding -> scores in log2.
// ---------------------------------------------------------------------------
#define FQT   128
#define FKT   64
#define QSTR  68
#define KSTR  68
#define VSTR  72
#define PSTR  68
#define SM_Q  0
#define SM_K  (FQT * QSTR)                  // 8704
#define SM_V  (SM_K + FKT * KSTR)           // 13056
#define SM_P  (SM_V + FKT * VSTR)           // 17664
#define ATT_SMEM ((SM_P + FQT * PSTR) * 4)  // 105472 bytes

__global__ __launch_bounds__(256, 1)
void flash_attn_mma(const float* __restrict__ Q,
                    const float* __restrict__ Km,
                    const float* __restrict__ Vm,
                    float* __restrict__ ctx) {
    extern __shared__ uint32_t smf[];
    uint32_t* Qs = smf + SM_Q;
    uint32_t* Ks = smf + SM_K;
    uint32_t* Vs = smf + SM_V;
    uint32_t* Ps = smf + SM_P;

    const int tid  = threadIdx.x;
    const int lane = tid & 31;
    const int wid  = tid >> 5;
    const int g    = lane >> 2;
    const int t    = lane & 3;
    const int qb   = wid * 16;          // warp's q-row base within tile
    const int qt   = blockIdx.x;        // q tile (0..15)
    const int bh   = blockIdx.y;        // 0..31
    const int b    = bh >> 4;
    const int h    = bh & 15;

    const float SCLL2E = 0.125f * 1.44269504088896f;  // fold scale+log2e into Q

    // ---- Load Q tile (pre-scaled, tf32-rounded) ----
    {
        const int r  = tid >> 1;              // 0..127
        const int c0 = (tid & 1) * 32;        // 0 or 32
        const float* Qg = Q + (size_t)(b * SEQ + qt * FQT + r) * DMODEL + h * DK + c0;
        #pragma unroll
        for (int j = 0; j < 8; j++) {
            float4 qv = *(const float4*)(Qg + j * 4);
            uint32_t* dst = Qs + r * QSTR + c0 + j * 4;
            dst[0] = f2tf32(qv.x * SCLL2E);
            dst[1] = f2tf32(qv.y * SCLL2E);
            dst[2] = f2tf32(qv.z * SCLL2E);
            dst[3] = f2tf32(qv.w * SCLL2E);
        }
    }

    float oacc[8][4];
    #pragma unroll
    for (int ni = 0; ni < 8; ni++)
        #pragma unroll
        for (int r = 0; r < 4; r++) oacc[ni][r] = 0.0f;
    float m0 = -1e30f, m1 = -1e30f, l0 = 0.0f, l1 = 0.0f;

    // K/V loader mapping: row = tid>>2 (0..63), cols (tid&3)*16 + 0..15
    const int kvr = tid >> 2;
    const int kvc = (tid & 3) * 16;

    for (int kt = 0; kt < SEQ / FKT; kt++) {
        __syncthreads();   // prev iteration's PV reads of Ps/Vs done; Qs visible (iter 0)

        // ---- Load K and V tiles (tf32-rounded) ----
        {
            const float* Kg = Km + (size_t)(b * SEQ + kt * FKT + kvr) * DMODEL + h * DK + kvc;
            const float* Vg = Vm + (size_t)(b * SEQ + kt * FKT + kvr) * DMODEL + h * DK + kvc;
            #pragma unroll
            for (int j = 0; j < 4; j++) {
                float4 kv = *(const float4*)(Kg + j * 4);
                float4 vv = *(const float4*)(Vg + j * 4);
                uint32_t* kd = Ks + kvr * KSTR + kvc + j * 4;
                uint32_t* vd = Vs + kvr * VSTR + kvc + j * 4;
                kd[0] = f2tf32(kv.x); kd[1] = f2tf32(kv.y);
                kd[2] = f2tf32(kv.z); kd[3] = f2tf32(kv.w);
                vd[0] = f2tf32(vv.x); vd[1] = f2tf32(vv.y);
                vd[2] = f2tf32(vv.z); vd[3] = f2tf32(vv.w);
            }
        }
        __syncthreads();

        // ---- S = Q K^T (in log2 domain; warp computes 16x64) ----
        float s[8][4];
        #pragma unroll
        for (int ni = 0; ni < 8; ni++)
            #pragma unroll
            for (int r = 0; r < 4; r++) s[ni][r] = 0.0f;

        #pragma unroll
        for (int ks = 0; ks < 8; ks++) {
            const int kc = ks * 8 + t;
            uint32_t a[4];
            a[0] = Qs[(qb + g    ) * QSTR + kc];
            a[1] = Qs[(qb + g + 8) * QSTR + kc];
            a[2] = Qs[(qb + g    ) * QSTR + kc + 4];
            a[3] = Qs[(qb + g + 8) * QSTR + kc + 4];
            #pragma unroll
            for (int ni = 0; ni < 8; ni++) {
                uint32_t bb[2];
                bb[0] = Ks[(ni * 8 + g) * KSTR + kc];
                bb[1] = Ks[(ni * 8 + g) * KSTR + kc + 4];
                mma_tf32(s[ni], a, bb);
            }
        }

        // ---- Online softmax (rows qb+g and qb+g+8; reduce over 4-lane t-group) ----
        float tm0 = -1e30f, tm1 = -1e30f;
        #pragma unroll
        for (int ni = 0; ni < 8; ni++) {
            tm0 = fmaxf(tm0, fmaxf(s[ni][0], s[ni][1]));
            tm1 = fmaxf(tm1, fmaxf(s[ni][2], s[ni][3]));
        }
        tm0 = fmaxf(tm0, __shfl_xor_sync(0xffffffffu, tm0, 1));
        tm0 = fmaxf(tm0, __shfl_xor_sync(0xffffffffu, tm0, 2));
        tm1 = fmaxf(tm1, __shfl_xor_sync(0xffffffffu, tm1, 1));
        tm1 = fmaxf(tm1, __shfl_xor_sync(0xffffffffu, tm1, 2));

        const float mn0 = fmaxf(m0, tm0);
        const float mn1 = fmaxf(m1, tm1);
        const float c0 = fexp2(m0 - mn0);
        const float c1 = fexp2(m1 - mn1);
        m0 = mn0; m1 = mn1;

        float rs0 = 0.0f, rs1 = 0.0f;
        #pragma unroll
        for (int ni = 0; ni < 8; ni++) {
            float p0 = fexp2(s[ni][0] - mn0);
            float p1 = fexp2(s[ni][1] - mn0);
            float p2 = fexp2(s[ni][2] - mn1);
            float p3 = fexp2(s[ni][3] - mn1);
            rs0 += p0 + p1;
            rs1 += p2 + p3;
            const int cc = ni * 8 + 2 * t;
            *(uint2*)(Ps + (qb + g    ) * PSTR + cc) = make_uint2(f2tf32(p0), f2tf32(p1));
            *(uint2*)(Ps + (qb + g + 8) * PSTR + cc) = make_uint2(f2tf32(p2), f2tf32(p3));
        }
        rs0 += __shfl_xor_sync(0xffffffffu, rs0, 1);
        rs0 += __shfl_xor_sync(0xffffffffu, rs0, 2);
        rs1 += __shfl_xor_sync(0xffffffffu, rs1, 1);
        rs1 += __shfl_xor_sync(0xffffffffu, rs1, 2);
        l0 = l0 * c0 + rs0;
        l1 = l1 * c1 + rs1;

        #pragma unroll
        for (int ni = 0; ni < 8; ni++) {
            oacc[ni][0] *= c0; oacc[ni][1] *= c0;
            oacc[ni][2] *= c1; oacc[ni][3] *= c1;
        }
        __syncthreads();   // Ps visible to all lanes

        // ---- O += P V ----
        #pragma unroll
        for (int ks = 0; ks < 8; ks++) {
            const int kc = ks * 8 + t;
            uint32_t a[4];
            a[0] = Ps[(qb + g    ) * PSTR + kc];
            a[1] = Ps[(qb + g + 8) * PSTR + kc];
            a[2] = Ps[(qb + g    ) * PSTR + kc + 4];
            a[3] = Ps[(qb + g + 8) * PSTR + kc + 4];
            #pragma unroll
            for (int ni = 0; ni < 8; ni++) {
                uint32_t bb[2];
                bb[0] = Vs[(ks * 8 + t    ) * VSTR + ni * 8 + g];
                bb[1] = Vs[(ks * 8 + t + 4) * VSTR + ni * 8 + g];
                mma_tf32(oacc[ni], a, bb);
            }
        }
    }

    // ---- Normalize and write ctx ----
    const float inv0 = 1.0f / l0;
    const float inv1 = 1.0f / l1;
    const int r0 = b * SEQ + qt * FQT + qb + g;
    #pragma unroll
    for (int ni = 0; ni < 8; ni++) {
        const int cc = h * DK + ni * 8 + 2 * t;
        *(float2*)(ctx + (size_t)r0 * DMODEL + cc) =
            make_float2(oacc[ni][0] * inv0, oacc[ni][1] * inv0);
        *(float2*)(ctx + (size_t)(r0 + 8) * DMODEL + cc) =
            make_float2(oacc[ni][2] * inv1, oacc[ni][3] * inv1);
    }
}

// ---------------------------------------------------------------------------
// Launch
// ---------------------------------------------------------------------------
extern "C" void kernel_launch(void* const* d_in, const int* in_sizes, int n_in,
                              void* d_out, int out_size) {
    const float* q   = (const float*)d_in[0];
    const float* k   = (const float*)d_in[1];
    const float* v   = (const float*)d_in[2];
    const float* w_q = (const float*)d_in[3];
    const float* w_k = (const float*)d_in[4];
    const float* w_v = (const float*)d_in[5];
    const float* w_o = (const float*)d_in[6];
    const float* b_q = (const float*)d_in[7];
    const float* b_k = (const float*)d_in[8];
    const float* b_v = (const float*)d_in[9];
    const float* b_o = (const float*)d_in[10];
    float* out = (float*)d_out;

    float *gq, *gk, *gv, *gctx;
    cudaGetSymbolAddress((void**)&gq,   g_q);
    cudaGetSymbolAddress((void**)&gk,   g_k);
    cudaGetSymbolAddress((void**)&gv,   g_v);
    cudaGetSymbolAddress((void**)&gctx, g_ctx);

    cudaFuncSetAttribute(flash_attn_mma, cudaFuncAttributeMaxDynamicSharedMemorySize, ATT_SMEM);

    dim3 gg(DMODEL / 128, MROWS / 128);   // (8, 32)

    gemm_mma<<<gg, 256>>>(q, w_q, b_q, gq);
    gemm_mma<<<gg, 256>>>(k, w_k, b_k, gk);
    gemm_mma<<<gg, 256>>>(v, w_v, b_v, gv);

    dim3 ag(SEQ / FQT, BATCH * NHEADS);   // (16, 32)
    flash_attn_mma<<<ag, 256, ATT_SMEM>>>(gq, gk, gv, gctx);

    gemm_mma<<<gg, 256>>>(gctx, w_o, b_o, out);
}